// round 8
// baseline (speedup 1.0000x reference)
#include <cuda_runtime.h>

// StyleGAN 3D x2 upsample, separable [1,4,6,4,1]/16 * 2 per axis.
// Per axis: out[2m]   = 0.5*(x[m-1] + x[m])
//           out[2m+1] = 0.125*x[m-1] + 0.75*x[m] + 0.125*x[m+1]
//
// Stage A: raw input tile -> smem. Stage B: rolling 3-row ring, W+H fused,
// D-pass staged in smem and drained via cp.async.bulk S->G (TMA pipe).
// TD=4 tile: 37.2KB smem -> 6 blocks/SM, 4 serial iterations per block.

#define DIN   48
#define DOUT  96
#define TD    4            // input-d per block
#define TH    8            // input-h per block
#define SD    6            // TD + 2 halo
#define SHH   10           // TH + 2 halo
#define SWR   56           // zeros[0..3], x[4..51], zeros[52..55]

__device__ __forceinline__ unsigned sm32(const void* p) {
    return (unsigned)__cvta_generic_to_shared(p);
}

__global__ __launch_bounds__(192, 6)
void upsample3d_kernel(const float* __restrict__ in, float* __restrict__ out)
{
    __shared__ float s2[SD][SHH][SWR];            // raw input tile (13.1 KB)
    __shared__ float stg[2][2][2 * TH][DOUT];     // staging: 2 bufs x 2 d-planes (24 KB)

    const int tx = threadIdx.x;            // 0..23  (output w quad = 4tx)
    const int ty = threadIdx.y;            // 0..7   (input h in tile)
    const int h0 = blockIdx.x * TH;
    const int d0 = blockIdx.y * TD;
    const int nc = blockIdx.z;             // fused N*C = 128

    const float* __restrict__ src = in  + (size_t)nc * (DIN * DIN * DIN);
    float*       __restrict__ dst = out + (size_t)nc * ((size_t)DOUT * DOUT * DOUT);

    const int tid = ty * 24 + tx;          // 0..191

    // ================= Stage A: raw fill (720 float4 tasks) =================
    #pragma unroll
    for (int it = 0; it < 4; it++) {
        const int i  = tid + it * 192;     // 0..767
        if (i < SD * SHH * 12) {
            const int c  = i % 12;
            const int r  = i / 12;
            const int rh = r % SHH;
            const int rd = r / SHH;
            const int h  = rh - 1 + h0;
            const int d  = rd - 1 + d0;
            float4 v = make_float4(0.f, 0.f, 0.f, 0.f);
            if ((unsigned)h < DIN && (unsigned)d < DIN)
                v = *(const float4*)&src[((size_t)d * DIN + h) * DIN + 4 * c];
            *(float4*)&s2[rd][rh][4 + 4 * c] = v;
        }
    }
    if (tid < SD * SHH * 2) {              // w-halo pads
        const int r = tid >> 1;
        *(float4*)&s2[r / SHH][r % SHH][(tid & 1) ? 52 : 0] =
            make_float4(0.f, 0.f, 0.f, 0.f);
    }
    __syncthreads();

    // ================= Stage B: W+H+D rolling ring, bulk-copied out =========
    const int wb = 2 * tx + 3;             // s2 index of x[2tx-1]
    float4 hv[3][2];                       // ring of H results (even-h, odd-h)

    #pragma unroll
    for (int i = 0; i < SD; i++) {
        // ---- W then H for d-window row i (once per row) ----
        float4 w[3];
        #pragma unroll
        for (int j = 0; j < 3; j++) {
            const float* row = s2[i][ty + j];
            float  a  = row[wb];                          // x[2tx-1]
            float2 bc = *(const float2*)&row[wb + 1];     // x[2tx], x[2tx+1]
            float  dd = row[wb + 3];                      // x[2tx+2]
            w[j].x = 0.5f  * (a + bc.x);
            w[j].y = 0.75f * bc.x + 0.125f * (a + bc.y);
            w[j].z = 0.5f  * (bc.x + bc.y);
            w[j].w = 0.75f * bc.y + 0.125f * (bc.x + dd);
        }
        {
            float4 e, o;
            e.x = 0.5f * (w[0].x + w[1].x);  o.x = 0.75f * w[1].x + 0.125f * (w[0].x + w[2].x);
            e.y = 0.5f * (w[0].y + w[1].y);  o.y = 0.75f * w[1].y + 0.125f * (w[0].y + w[2].y);
            e.z = 0.5f * (w[0].z + w[1].z);  o.z = 0.75f * w[1].z + 0.125f * (w[0].z + w[2].z);
            e.w = 0.5f * (w[0].w + w[1].w);  o.w = 0.75f * w[1].w + 0.125f * (w[0].w + w[2].w);
            hv[i % 3][0] = e;
            hv[i % 3][1] = o;
        }

        // ---- D-pass for output pair p = i-2 ----
        if (i >= 2) {
            const int p   = i - 2;         // 0..TD-1 (compile-time after unroll)
            const int buf = p & 1;

            float4 vE[2], vO[2];
            #pragma unroll
            for (int hs = 0; hs < 2; hs++) {
                float4 A = hv[(i - 2) % 3][hs];
                float4 B = hv[(i - 1) % 3][hs];
                float4 C = hv[i % 3][hs];
                vE[hs].x = 0.5f * (A.x + B.x);  vO[hs].x = 0.75f * B.x + 0.125f * (A.x + C.x);
                vE[hs].y = 0.5f * (A.y + B.y);  vO[hs].y = 0.75f * B.y + 0.125f * (A.y + C.y);
                vE[hs].z = 0.5f * (A.z + B.z);  vO[hs].z = 0.75f * B.z + 0.125f * (A.z + C.z);
                vE[hs].w = 0.5f * (A.w + B.w);  vO[hs].w = 0.75f * B.w + 0.125f * (A.w + C.w);
            }

            // buffer (p&1) was consumed by bulk group p-2; wait for its reads
            if (p >= 2 && tid == 0)
                asm volatile("cp.async.bulk.wait_group.read 1;" ::: "memory");
            __syncthreads();

            #pragma unroll
            for (int hs = 0; hs < 2; hs++) {
                *(float4*)&stg[buf][0][2 * ty + hs][4 * tx] = vE[hs];
                *(float4*)&stg[buf][1][2 * ty + hs][4 * tx] = vO[hs];
            }
            __syncthreads();

            if (tid == 0) {
                asm volatile("fence.proxy.async.shared::cta;" ::: "memory");
                const int od = 2 * (d0 + p);
                float* g0 = dst + ((size_t)od * DOUT + 2 * h0) * DOUT;
                float* g1 = g0 + (size_t)DOUT * DOUT;
                asm volatile(
                    "cp.async.bulk.global.shared::cta.bulk_group [%0], [%1], %2;"
                    :: "l"(g0), "r"(sm32(&stg[buf][0][0][0])),
                       "r"(2 * TH * DOUT * 4) : "memory");
                asm volatile(
                    "cp.async.bulk.global.shared::cta.bulk_group [%0], [%1], %2;"
                    :: "l"(g1), "r"(sm32(&stg[buf][1][0][0])),
                       "r"(2 * TH * DOUT * 4) : "memory");
                asm volatile("cp.async.bulk.commit_group;" ::: "memory");
            }
        }
    }

    // drain all outstanding bulk stores before exit
    if (tid == 0)
        asm volatile("cp.async.bulk.wait_group 0;" ::: "memory");
}

extern "C" void kernel_launch(void* const* d_in, const int* in_sizes, int n_in,
                              void* d_out, int out_size)
{
    const float* x = (const float*)d_in[0];
    float* y = (float*)d_out;
    dim3 block(24, 8, 1);                        // 192 threads
    dim3 grid(DIN / TH, DIN / TD, 128);          // 6 x 12 x (N*C) = 9216 blocks
    upsample3d_kernel<<<grid, block>>>(x, y);
}

// round 9
// speedup vs baseline: 1.1299x; 1.1299x over previous
#include <cuda_runtime.h>

// StyleGAN 3D x2 upsample, separable [1,4,6,4,1]/16 * 2 per axis.
// Per axis: out[2m]   = 0.5*(x[m-1] + x[m])
//           out[2m+1] = 0.125*x[m-1] + 0.75*x[m] + 0.125*x[m+1]
//
// Stage A: raw input tile -> smem. Stage B: rolling 3-row ring, W+H fused,
// D-pass staged in a SINGLE 12KB smem buffer drained via cp.async.bulk S->G.
// wait_group.read 0 only waits for TMA's smem *read* (~100cyc), so one buffer
// pipelines almost as well as two while halving staging smem:
// total 25.2KB -> 8 blocks/SM (48 warps) to cover the in-loop barrier stalls.

#define DIN   48
#define DOUT  96
#define TD    6            // input-d per block
#define TH    8            // input-h per block
#define SD    8            // TD + 2 halo
#define SHH   10           // TH + 2 halo
#define SWR   56           // zeros[0..3], x[4..51], zeros[52..55]

__device__ __forceinline__ unsigned sm32(const void* p) {
    return (unsigned)__cvta_generic_to_shared(p);
}

__global__ __launch_bounds__(192, 8)
void upsample3d_kernel(const float* __restrict__ in, float* __restrict__ out)
{
    __shared__ float s2[SD][SHH][SWR];            // raw input tile (13.1 KB)
    __shared__ float stg[2][2 * TH][DOUT];        // staging: 2 d-planes (12 KB)

    const int tx = threadIdx.x;            // 0..23  (output w quad = 4tx)
    const int ty = threadIdx.y;            // 0..7   (input h in tile)
    const int h0 = blockIdx.x * TH;
    const int d0 = blockIdx.y * TD;
    const int nc = blockIdx.z;             // fused N*C = 128

    const float* __restrict__ src = in  + (size_t)nc * (DIN * DIN * DIN);
    float*       __restrict__ dst = out + (size_t)nc * ((size_t)DOUT * DOUT * DOUT);

    const int tid = ty * 24 + tx;          // 0..191

    // ================= Stage A: raw fill (960 float4 tasks = 5/thread) =====
    #pragma unroll
    for (int it = 0; it < 5; it++) {
        const int i  = tid + it * 192;     // 0..959
        const int c  = i % 12;
        const int r  = i / 12;
        const int rh = r % SHH;
        const int rd = r / SHH;
        const int h  = rh - 1 + h0;
        const int d  = rd - 1 + d0;
        float4 v = make_float4(0.f, 0.f, 0.f, 0.f);
        if ((unsigned)h < DIN && (unsigned)d < DIN)
            v = *(const float4*)&src[((size_t)d * DIN + h) * DIN + 4 * c];
        *(float4*)&s2[rd][rh][4 + 4 * c] = v;
    }
    if (tid < SD * SHH * 2) {              // w-halo pads
        const int r = tid >> 1;
        *(float4*)&s2[r / SHH][r % SHH][(tid & 1) ? 52 : 0] =
            make_float4(0.f, 0.f, 0.f, 0.f);
    }
    __syncthreads();

    // ================= Stage B: W+H+D rolling ring, bulk-copied out ========
    const int wb = 2 * tx + 3;             // s2 index of x[2tx-1]
    float4 hv[3][2];                       // ring of H results (even-h, odd-h)

    #pragma unroll
    for (int i = 0; i < SD; i++) {
        // ---- W then H for d-window row i (once per row) ----
        float4 w[3];
        #pragma unroll
        for (int j = 0; j < 3; j++) {
            const float* row = s2[i][ty + j];
            float  a  = row[wb];                          // x[2tx-1]
            float2 bc = *(const float2*)&row[wb + 1];     // x[2tx], x[2tx+1]
            float  dd = row[wb + 3];                      // x[2tx+2]
            w[j].x = 0.5f  * (a + bc.x);
            w[j].y = 0.75f * bc.x + 0.125f * (a + bc.y);
            w[j].z = 0.5f  * (bc.x + bc.y);
            w[j].w = 0.75f * bc.y + 0.125f * (bc.x + dd);
        }
        {
            float4 e, o;
            e.x = 0.5f * (w[0].x + w[1].x);  o.x = 0.75f * w[1].x + 0.125f * (w[0].x + w[2].x);
            e.y = 0.5f * (w[0].y + w[1].y);  o.y = 0.75f * w[1].y + 0.125f * (w[0].y + w[2].y);
            e.z = 0.5f * (w[0].z + w[1].z);  o.z = 0.75f * w[1].z + 0.125f * (w[0].z + w[2].z);
            e.w = 0.5f * (w[0].w + w[1].w);  o.w = 0.75f * w[1].w + 0.125f * (w[0].w + w[2].w);
            hv[i % 3][0] = e;
            hv[i % 3][1] = o;
        }

        // ---- D-pass for output pair p = i-2 ----
        if (i >= 2) {
            const int p = i - 2;           // 0..TD-1 (compile-time after unroll)

            float4 vE[2], vO[2];
            #pragma unroll
            for (int hs = 0; hs < 2; hs++) {
                float4 A = hv[(i - 2) % 3][hs];
                float4 B = hv[(i - 1) % 3][hs];
                float4 C = hv[i % 3][hs];
                vE[hs].x = 0.5f * (A.x + B.x);  vO[hs].x = 0.75f * B.x + 0.125f * (A.x + C.x);
                vE[hs].y = 0.5f * (A.y + B.y);  vO[hs].y = 0.75f * B.y + 0.125f * (A.y + C.y);
                vE[hs].z = 0.5f * (A.z + B.z);  vO[hs].z = 0.75f * B.z + 0.125f * (A.z + C.z);
                vE[hs].w = 0.5f * (A.w + B.w);  vO[hs].w = 0.75f * B.w + 0.125f * (A.w + C.w);
            }

            // wait until TMA has finished READING the staging buffer from the
            // previous iteration (smem-read completion, not gmem landing)
            if (p >= 1 && tid == 0)
                asm volatile("cp.async.bulk.wait_group.read 0;" ::: "memory");
            __syncthreads();

            #pragma unroll
            for (int hs = 0; hs < 2; hs++) {
                *(float4*)&stg[0][2 * ty + hs][4 * tx] = vE[hs];
                *(float4*)&stg[1][2 * ty + hs][4 * tx] = vO[hs];
            }
            __syncthreads();

            if (tid == 0) {
                asm volatile("fence.proxy.async.shared::cta;" ::: "memory");
                const int od = 2 * (d0 + p);
                float* g0 = dst + ((size_t)od * DOUT + 2 * h0) * DOUT;
                float* g1 = g0 + (size_t)DOUT * DOUT;
                asm volatile(
                    "cp.async.bulk.global.shared::cta.bulk_group [%0], [%1], %2;"
                    :: "l"(g0), "r"(sm32(&stg[0][0][0])),
                       "r"(2 * TH * DOUT * 4) : "memory");
                asm volatile(
                    "cp.async.bulk.global.shared::cta.bulk_group [%0], [%1], %2;"
                    :: "l"(g1), "r"(sm32(&stg[1][0][0])),
                       "r"(2 * TH * DOUT * 4) : "memory");
                asm volatile("cp.async.bulk.commit_group;" ::: "memory");
            }
        }
    }

    // drain all outstanding bulk stores before exit
    if (tid == 0)
        asm volatile("cp.async.bulk.wait_group 0;" ::: "memory");
}

extern "C" void kernel_launch(void* const* d_in, const int* in_sizes, int n_in,
                              void* d_out, int out_size)
{
    const float* x = (const float*)d_in[0];
    float* y = (float*)d_out;
    dim3 block(24, 8, 1);                        // 192 threads
    dim3 grid(DIN / TH, DIN / TD, 128);          // 6 x 8 x (N*C) = 6144 blocks
    upsample3d_kernel<<<grid, block>>>(x, y);
}

// round 10
// speedup vs baseline: 1.1542x; 1.0215x over previous
#include <cuda_runtime.h>

// StyleGAN 3D x2 upsample, separable [1,4,6,4,1]/16 * 2 per axis.
// Per axis: out[2m]   = 0.5*(x[m-1] + x[m])
//           out[2m+1] = 0.125*x[m-1] + 0.75*x[m] + 0.125*x[m+1]
//
// Stage A: raw input tile -> smem via cp.async (LDGSTS, zfill for OOB).
// Stage B: rolling 3-row ring, W+H fused; D-pass staged in double-buffered
// smem and drained via cp.async.bulk S->G on the TMA pipe.
// TD=8: fill + prologue amortized over 8 output pairs.

#define DIN   48
#define DOUT  96
#define TD    8            // input-d per block
#define TH    8            // input-h per block
#define SD    10           // TD + 2 halo
#define SHH   10           // TH + 2 halo
#define SWR   56           // zeros[0..3], x[4..51], zeros[52..55]

__device__ __forceinline__ unsigned sm32(const void* p) {
    return (unsigned)__cvta_generic_to_shared(p);
}

__global__ __launch_bounds__(192, 4)
void upsample3d_kernel(const float* __restrict__ in, float* __restrict__ out)
{
    __shared__ float s2[SD][SHH][SWR];            // raw input tile (21.9 KB)
    __shared__ float stg[2][2][2 * TH][DOUT];     // staging: 2 bufs x 2 planes (24 KB)

    const int tx = threadIdx.x;            // 0..23  (output w quad = 4tx)
    const int ty = threadIdx.y;            // 0..7   (input h in tile)
    const int h0 = blockIdx.x * TH;
    const int d0 = blockIdx.y * TD;
    const int nc = blockIdx.z;             // fused N*C = 128

    const float* __restrict__ src = in  + (size_t)nc * (DIN * DIN * DIN);
    float*       __restrict__ dst = out + (size_t)nc * ((size_t)DOUT * DOUT * DOUT);

    const int tid = ty * 24 + tx;          // 0..191

    // ================= Stage A: async fill (1200 float4 tasks) ==============
    for (int i = tid; i < SD * SHH * 12; i += 192) {
        const int c  = i % 12;
        const int r  = i / 12;
        const int rh = r % SHH;
        const int rd = r / SHH;
        const int h  = rh - 1 + h0;
        const int d  = rd - 1 + d0;
        const bool ok = ((unsigned)h < DIN) && ((unsigned)d < DIN);
        const float* gp = src + ((size_t)d * DIN + h) * DIN + 4 * c;  // safe to form
        const unsigned sp = sm32(&s2[rd][rh][4 + 4 * c]);
        const int nbytes = ok ? 16 : 0;    // zfill when OOB
        asm volatile("cp.async.ca.shared.global [%0], [%1], 16, %2;"
                     :: "r"(sp), "l"(gp), "r"(nbytes) : "memory");
    }
    // w-halo pads (always zero)
    for (int i = tid; i < SD * SHH * 2; i += 192) {
        const int r = i >> 1;
        *(float4*)&s2[r / SHH][r % SHH][(i & 1) ? 52 : 0] =
            make_float4(0.f, 0.f, 0.f, 0.f);
    }
    asm volatile("cp.async.commit_group;" ::: "memory");
    asm volatile("cp.async.wait_group 0;" ::: "memory");
    __syncthreads();

    // ================= Stage B: W+H+D rolling ring, bulk-copied out =========
    const int wb = 2 * tx + 3;             // s2 index of x[2tx-1]
    float4 hv[3][2];                       // ring of H results (even-h, odd-h)

    #pragma unroll
    for (int i = 0; i < SD; i++) {
        // ---- W then H for d-window row i (once per row) ----
        float4 w[3];
        #pragma unroll
        for (int j = 0; j < 3; j++) {
            const float* row = s2[i][ty + j];
            float  a  = row[wb];                          // x[2tx-1]
            float2 bc = *(const float2*)&row[wb + 1];     // x[2tx], x[2tx+1]
            float  dd = row[wb + 3];                      // x[2tx+2]
            w[j].x = 0.5f  * (a + bc.x);
            w[j].y = 0.75f * bc.x + 0.125f * (a + bc.y);
            w[j].z = 0.5f  * (bc.x + bc.y);
            w[j].w = 0.75f * bc.y + 0.125f * (bc.x + dd);
        }
        {
            float4 e, o;
            e.x = 0.5f * (w[0].x + w[1].x);  o.x = 0.75f * w[1].x + 0.125f * (w[0].x + w[2].x);
            e.y = 0.5f * (w[0].y + w[1].y);  o.y = 0.75f * w[1].y + 0.125f * (w[0].y + w[2].y);
            e.z = 0.5f * (w[0].z + w[1].z);  o.z = 0.75f * w[1].z + 0.125f * (w[0].z + w[2].z);
            e.w = 0.5f * (w[0].w + w[1].w);  o.w = 0.75f * w[1].w + 0.125f * (w[0].w + w[2].w);
            hv[i % 3][0] = e;
            hv[i % 3][1] = o;
        }

        // ---- D-pass for output pair p = i-2 ----
        if (i >= 2) {
            const int p   = i - 2;         // 0..TD-1 (compile-time after unroll)
            const int buf = p & 1;

            float4 vE[2], vO[2];
            #pragma unroll
            for (int hs = 0; hs < 2; hs++) {
                float4 A = hv[(i - 2) % 3][hs];
                float4 B = hv[(i - 1) % 3][hs];
                float4 C = hv[i % 3][hs];
                vE[hs].x = 0.5f * (A.x + B.x);  vO[hs].x = 0.75f * B.x + 0.125f * (A.x + C.x);
                vE[hs].y = 0.5f * (A.y + B.y);  vO[hs].y = 0.75f * B.y + 0.125f * (A.y + C.y);
                vE[hs].z = 0.5f * (A.z + B.z);  vO[hs].z = 0.75f * B.z + 0.125f * (A.z + C.z);
                vE[hs].w = 0.5f * (A.w + B.w);  vO[hs].w = 0.75f * B.w + 0.125f * (A.w + C.w);
            }

            // buffer (p&1) was consumed by bulk group p-2; wait for its reads
            if (p >= 2 && tid == 0)
                asm volatile("cp.async.bulk.wait_group.read 1;" ::: "memory");
            __syncthreads();

            #pragma unroll
            for (int hs = 0; hs < 2; hs++) {
                *(float4*)&stg[buf][0][2 * ty + hs][4 * tx] = vE[hs];
                *(float4*)&stg[buf][1][2 * ty + hs][4 * tx] = vO[hs];
            }
            __syncthreads();

            if (tid == 0) {
                asm volatile("fence.proxy.async.shared::cta;" ::: "memory");
                const int od = 2 * (d0 + p);
                float* g0 = dst + ((size_t)od * DOUT + 2 * h0) * DOUT;
                float* g1 = g0 + (size_t)DOUT * DOUT;
                asm volatile(
                    "cp.async.bulk.global.shared::cta.bulk_group [%0], [%1], %2;"
                    :: "l"(g0), "r"(sm32(&stg[buf][0][0][0])),
                       "r"(2 * TH * DOUT * 4) : "memory");
                asm volatile(
                    "cp.async.bulk.global.shared::cta.bulk_group [%0], [%1], %2;"
                    :: "l"(g1), "r"(sm32(&stg[buf][1][0][0])),
                       "r"(2 * TH * DOUT * 4) : "memory");
                asm volatile("cp.async.bulk.commit_group;" ::: "memory");
            }
        }
    }

    // drain all outstanding bulk stores before exit
    if (tid == 0)
        asm volatile("cp.async.bulk.wait_group 0;" ::: "memory");
}

extern "C" void kernel_launch(void* const* d_in, const int* in_sizes, int n_in,
                              void* d_out, int out_size)
{
    const float* x = (const float*)d_in[0];
    float* y = (float*)d_out;
    dim3 block(24, 8, 1);                        // 192 threads
    dim3 grid(DIN / TH, DIN / TD, 128);          // 6 x 6 x (N*C) = 4608 blocks
    upsample3d_kernel<<<grid, block>>>(x, y);
}